// round 6
// baseline (speedup 1.0000x reference)
#include <cuda_runtime.h>
#include <cstdint>

// Problem constants
#define B_SAMPLES  4096
#define D_DIM      768
#define N_CLASSES  1000
#define MAX_STAGES 4
#define MAX_P      8
#define SHARED_P   16

#define D_VEC (D_DIM / 4)        // 192 float4 per row

// Scratch (allocation-free)
__device__ float g_shared_mean[MAX_STAGES * D_DIM];
__device__ int4  g_desc[B_SAMPLES];   // {pair, cnt, bits(0.5/max(cnt,1)), stage}

// ---------------------------------------------------------------------------
// Prep kernel: pack per-sample descriptors (with precomputed scale) +
// shared-stage means.
// ---------------------------------------------------------------------------
__global__ __launch_bounds__(256)
void prep_kernel(const float* __restrict__ shared_protos,
                 const int*   __restrict__ class_ids,
                 const int*   __restrict__ stages,
                 const int*   __restrict__ proto_counts) {
    int blk = blockIdx.x;
    int t   = threadIdx.x;

    if (blk < 16) {
        int b = blk * 256 + t;
        int cid  = class_ids[b];
        int st   = stages[b];
        int pair = cid * MAX_STAGES + st;
        int cnt  = proto_counts[pair];
        float inv = 0.5f / (float)max(cnt, 1);
        g_desc[b] = make_int4(pair, cnt, __float_as_int(inv), st);
    } else {
        int st = blk - 16;
        if (t < D_VEC) {
            const float4* src = reinterpret_cast<const float4*>(
                shared_protos + (size_t)st * SHARED_P * D_DIM);
            float4 acc = make_float4(0.f, 0.f, 0.f, 0.f);
#pragma unroll
            for (int p = 0; p < SHARED_P; ++p) {
                float4 x = src[p * D_VEC + t];
                acc.x += x.x; acc.y += x.y; acc.z += x.z; acc.w += x.w;
            }
            const float inv = 1.0f / (float)SHARED_P;
            acc.x *= inv; acc.y *= inv; acc.z *= inv; acc.w *= inv;
            reinterpret_cast<float4*>(g_shared_mean)[st * D_VEC + t] = acc;
        }
    }
}

// ---------------------------------------------------------------------------
// Main kernel: one block per sample, 192 threads (one float4 lane each).
// Proto loads forced into distinct registers via volatile asm, issued as a
// back-to-back burst through a fall-through switch on (warp-uniform) cnt.
// ---------------------------------------------------------------------------
#define LDP(i)                                                              \
    asm volatile("ld.global.nc.v4.f32 {%0,%1,%2,%3}, [%4];"                \
                 : "=f"(x##i.x), "=f"(x##i.y), "=f"(x##i.z), "=f"(x##i.w)  \
                 : "l"(pbase + (i) * D_DIM));

__global__ __launch_bounds__(D_VEC)
void proto_pool_kernel(const float* __restrict__ features,
                       const float* __restrict__ class_protos,
                       float* __restrict__ out) {
    int b = blockIdx.x;
    int v = threadIdx.x;

    // 1) Feature load first — independent of everything, issued immediately.
    float4 f;
    const float* fptr = features + (size_t)b * D_DIM + v * 4;
    asm volatile("ld.global.cs.v4.f32 {%0,%1,%2,%3}, [%4];"
                 : "=f"(f.x), "=f"(f.y), "=f"(f.z), "=f"(f.w)
                 : "l"(fptr));

    // 2) Single 16-byte descriptor load (warp-broadcast).
    int4 dd = g_desc[b];
    int   pair = dd.x;
    int   cnt  = dd.y;
    float inv  = __int_as_float(dd.z);
    int   st   = dd.w;

    // 3) Shared-mean load (L2-resident, independent of protos).
    float4 sh = reinterpret_cast<const float4*>(g_shared_mean)[st * D_VEC + v];

    // 4) Proto burst: cnt back-to-back LDG.128 into distinct registers.
    const float* pbase = class_protos +
                         (size_t)pair * (MAX_P * D_DIM) + v * 4;
    float4 x0, x1, x2, x3, x4, x5, x6, x7;
    x0 = x1 = x2 = x3 = x4 = x5 = x6 = x7 = make_float4(0.f, 0.f, 0.f, 0.f);

    switch (cnt) {
        case 8: LDP(7)   /* fallthrough */
        case 7: LDP(6)   /* fallthrough */
        case 6: LDP(5)   /* fallthrough */
        case 5: LDP(4)   /* fallthrough */
        case 4: LDP(3)   /* fallthrough */
        case 3: LDP(2)   /* fallthrough */
        case 2: LDP(1)   /* fallthrough */
        case 1: LDP(0)
        default: break;
    }

    // 5) Tree sum.
    x0.x += x1.x; x0.y += x1.y; x0.z += x1.z; x0.w += x1.w;
    x2.x += x3.x; x2.y += x3.y; x2.z += x3.z; x2.w += x3.w;
    x4.x += x5.x; x4.y += x5.y; x4.z += x5.z; x4.w += x5.w;
    x6.x += x7.x; x6.y += x7.y; x6.z += x7.z; x6.w += x7.w;
    x0.x += x2.x; x0.y += x2.y; x0.z += x2.z; x0.w += x2.w;
    x4.x += x6.x; x4.y += x6.y; x4.z += x6.z; x4.w += x6.w;
    x0.x += x4.x; x0.y += x4.y; x0.z += x4.z; x0.w += x4.w;

    float4 r;
    r.x = f.x + 0.5f * sh.x + x0.x * inv;
    r.y = f.y + 0.5f * sh.y + x0.y * inv;
    r.z = f.z + 0.5f * sh.z + x0.z * inv;
    r.w = f.w + 0.5f * sh.w + x0.w * inv;

    float* optr = out + (size_t)b * D_DIM + v * 4;
    asm volatile("st.global.cs.v4.f32 [%0], {%1,%2,%3,%4};"
                 :: "l"(optr), "f"(r.x), "f"(r.y), "f"(r.z), "f"(r.w)
                 : "memory");
}

extern "C" void kernel_launch(void* const* d_in, const int* in_sizes, int n_in,
                              void* d_out, int out_size) {
    const float* features      = (const float*)d_in[0];
    const float* class_protos  = (const float*)d_in[1];
    const float* shared_protos = (const float*)d_in[2];
    const int*   class_ids     = (const int*)d_in[3];
    const int*   stages        = (const int*)d_in[4];
    const int*   proto_counts  = (const int*)d_in[5];
    float* out = (float*)d_out;

    prep_kernel<<<20, 256>>>(shared_protos, class_ids, stages, proto_counts);
    proto_pool_kernel<<<B_SAMPLES, D_VEC>>>(features, class_protos, out);
}

// round 8
// speedup vs baseline: 1.0216x; 1.0216x over previous
#include <cuda_runtime.h>
#include <cstdint>

// Problem constants
#define B_SAMPLES  4096
#define D_DIM      768
#define N_CLASSES  1000
#define MAX_STAGES 4
#define MAX_P      8
#define SHARED_P   16

#define D_VEC (D_DIM / 4)          // 192 float4 per row
#define TPB   96                   // 96 threads x 32B = 3072B = one row

// Scratch (allocation-free)
__device__ float g_shared_mean[MAX_STAGES * D_DIM];
__device__ int4  g_desc[B_SAMPLES];   // {pair, cnt, bits(0.5/max(cnt,1)), stage}

// ---------------------------------------------------------------------------
// Prep kernel: pack per-sample descriptors (with precomputed scale) +
// shared-stage means.
// ---------------------------------------------------------------------------
__global__ __launch_bounds__(256)
void prep_kernel(const float* __restrict__ shared_protos,
                 const int*   __restrict__ class_ids,
                 const int*   __restrict__ stages,
                 const int*   __restrict__ proto_counts) {
    int blk = blockIdx.x;
    int t   = threadIdx.x;

    if (blk < 16) {
        int b = blk * 256 + t;
        int cid  = class_ids[b];
        int st   = stages[b];
        int pair = cid * MAX_STAGES + st;
        int cnt  = proto_counts[pair];
        float inv = 0.5f / (float)max(cnt, 1);
        g_desc[b] = make_int4(pair, cnt, __float_as_int(inv), st);
    } else {
        int st = blk - 16;
        if (t < D_VEC) {
            const float4* src = reinterpret_cast<const float4*>(
                shared_protos + (size_t)st * SHARED_P * D_DIM);
            float4 acc = make_float4(0.f, 0.f, 0.f, 0.f);
#pragma unroll
            for (int p = 0; p < SHARED_P; ++p) {
                float4 x = src[p * D_VEC + t];
                acc.x += x.x; acc.y += x.y; acc.z += x.z; acc.w += x.w;
            }
            const float inv = 1.0f / (float)SHARED_P;
            acc.x *= inv; acc.y *= inv; acc.z *= inv; acc.w *= inv;
            reinterpret_cast<float4*>(g_shared_mean)[st * D_VEC + t] = acc;
        }
    }
}

// 256-bit proto load with L2 evict_last (form ptxas endorses on sm_103).
#define LDP256(i, row)                                                        \
    asm volatile("ld.global.nc.L2::evict_last.v8.b32 "                       \
                 "{%0,%1,%2,%3,%4,%5,%6,%7}, [%8];"                          \
                 : "=r"(x##i[0]), "=r"(x##i[1]), "=r"(x##i[2]), "=r"(x##i[3]),\
                   "=r"(x##i[4]), "=r"(x##i[5]), "=r"(x##i[6]), "=r"(x##i[7]) \
                 : "l"(pbase + (size_t)(row) * D_DIM));

// ---------------------------------------------------------------------------
// Main kernel: one block per sample, 96 threads (one 32B granule each).
// Branch-free: ALWAYS 8 back-to-back LDG.256 from clamped row indices
// (duplicates hit L1/L2), contributions masked by per-row weights.
// ---------------------------------------------------------------------------
__global__ __launch_bounds__(TPB)
void proto_pool_kernel(const float* __restrict__ features,
                       const float* __restrict__ class_protos,
                       float* __restrict__ out) {
    int b = blockIdx.x;
    int l = threadIdx.x;                 // 0..95, owns floats [l*8, l*8+8)

    // 1) Feature load first — independent, streaming (evict-first).
    float f[8];
    const float* fptr = features + (size_t)b * D_DIM + l * 8;
    asm volatile("ld.global.cs.v4.f32 {%0,%1,%2,%3}, [%4];"
                 : "=f"(f[0]), "=f"(f[1]), "=f"(f[2]), "=f"(f[3]) : "l"(fptr));
    asm volatile("ld.global.cs.v4.f32 {%0,%1,%2,%3}, [%4];"
                 : "=f"(f[4]), "=f"(f[5]), "=f"(f[6]), "=f"(f[7])
                 : "l"(fptr + 4));

    // 2) Descriptor (warp-broadcast, L2-hot).
    int4 dd = g_desc[b];
    int   pair = dd.x;
    int   cnt  = dd.y;
    float inv  = __int_as_float(dd.z);
    int   st   = dd.w;

    // 3) Proto burst: 8 unconditional LDG.256, rows clamped to [0, cnt-1].
    int cm1 = max(cnt - 1, 0);
    const float* pbase = class_protos + (size_t)pair * (MAX_P * D_DIM) + l * 8;

    uint32_t x0[8], x1[8], x2[8], x3[8], x4[8], x5[8], x6[8], x7[8];
    LDP256(0, 0)
    LDP256(1, min(1, cm1))
    LDP256(2, min(2, cm1))
    LDP256(3, min(3, cm1))
    LDP256(4, min(4, cm1))
    LDP256(5, min(5, cm1))
    LDP256(6, min(6, cm1))
    LDP256(7, min(7, cm1))

    // 4) Shared-mean (tiny, L2-resident).
    const float* shp = g_shared_mean + st * D_DIM + l * 8;
    float sh[8];
    asm volatile("ld.global.v4.f32 {%0,%1,%2,%3}, [%4];"
                 : "=f"(sh[0]), "=f"(sh[1]), "=f"(sh[2]), "=f"(sh[3])
                 : "l"(shp));
    asm volatile("ld.global.v4.f32 {%0,%1,%2,%3}, [%4];"
                 : "=f"(sh[4]), "=f"(sh[5]), "=f"(sh[6]), "=f"(sh[7])
                 : "l"(shp + 4));

    // 5) Per-row weights: inv for valid rows, 0 for clamped duplicates.
    float w0 = (0 < cnt) ? inv : 0.f;
    float w1 = (1 < cnt) ? inv : 0.f;
    float w2 = (2 < cnt) ? inv : 0.f;
    float w3 = (3 < cnt) ? inv : 0.f;
    float w4 = (4 < cnt) ? inv : 0.f;
    float w5 = (5 < cnt) ? inv : 0.f;
    float w6 = (6 < cnt) ? inv : 0.f;
    float w7 = (7 < cnt) ? inv : 0.f;

    // 6) Weighted accumulate per float j, consuming loads in issue order
    //    (scoreboard overlaps later loads with earlier FFMAs).
    float r[8];
#pragma unroll
    for (int j = 0; j < 8; ++j) {
        float a = f[j] + 0.5f * sh[j];
        float c = w1 * __uint_as_float(x1[j]);
        a += w0 * __uint_as_float(x0[j]);
        c += w3 * __uint_as_float(x3[j]);
        a += w2 * __uint_as_float(x2[j]);
        c += w5 * __uint_as_float(x5[j]);
        a += w4 * __uint_as_float(x4[j]);
        c += w7 * __uint_as_float(x7[j]);
        a += w6 * __uint_as_float(x6[j]);
        r[j] = a + c;
    }

    // 7) Streaming stores (evict-first).
    float* optr = out + (size_t)b * D_DIM + l * 8;
    asm volatile("st.global.cs.v4.f32 [%0], {%1,%2,%3,%4};"
                 :: "l"(optr), "f"(r[0]), "f"(r[1]), "f"(r[2]), "f"(r[3])
                 : "memory");
    asm volatile("st.global.cs.v4.f32 [%0], {%1,%2,%3,%4};"
                 :: "l"(optr + 4), "f"(r[4]), "f"(r[5]), "f"(r[6]), "f"(r[7])
                 : "memory");
}

extern "C" void kernel_launch(void* const* d_in, const int* in_sizes, int n_in,
                              void* d_out, int out_size) {
    const float* features      = (const float*)d_in[0];
    const float* class_protos  = (const float*)d_in[1];
    const float* shared_protos = (const float*)d_in[2];
    const int*   class_ids     = (const int*)d_in[3];
    const int*   stages        = (const int*)d_in[4];
    const int*   proto_counts  = (const int*)d_in[5];
    float* out = (float*)d_out;

    prep_kernel<<<20, 256>>>(shared_protos, class_ids, stages, proto_counts);
    proto_pool_kernel<<<B_SAMPLES, TPB>>>(features, class_protos, out);
}

// round 9
// speedup vs baseline: 1.1830x; 1.1579x over previous
#include <cuda_runtime.h>
#include <cstdint>

// Problem constants
#define B_SAMPLES  4096
#define D_DIM      768
#define N_CLASSES  1000
#define MAX_STAGES 4
#define MAX_P      8
#define SHARED_P   16

#define D_VEC (D_DIM / 4)          // 192 float4 per row
#define LPS   96                   // lanes per sample (96 x 32B = one row)
#define SPB   2                    // samples per block
#define TPB   (LPS * SPB)          // 192 threads

// Scratch (allocation-free)
__device__ float g_shared_mean[MAX_STAGES * D_DIM];
__device__ int4  g_desc[B_SAMPLES];   // {pair, cnt, bits(0.5/max(cnt,1)), stage}

// ---------------------------------------------------------------------------
// Prep kernel: pack per-sample descriptors (with precomputed scale) +
// shared-stage means.
// ---------------------------------------------------------------------------
__global__ __launch_bounds__(256)
void prep_kernel(const float* __restrict__ shared_protos,
                 const int*   __restrict__ class_ids,
                 const int*   __restrict__ stages,
                 const int*   __restrict__ proto_counts) {
    int blk = blockIdx.x;
    int t   = threadIdx.x;

    if (blk < 16) {
        int b = blk * 256 + t;
        int cid  = class_ids[b];
        int st   = stages[b];
        int pair = cid * MAX_STAGES + st;
        int cnt  = proto_counts[pair];
        float inv = 0.5f / (float)max(cnt, 1);
        g_desc[b] = make_int4(pair, cnt, __float_as_int(inv), st);
    } else {
        int st = blk - 16;
        if (t < D_VEC) {
            const float4* src = reinterpret_cast<const float4*>(
                shared_protos + (size_t)st * SHARED_P * D_DIM);
            float4 acc = make_float4(0.f, 0.f, 0.f, 0.f);
#pragma unroll
            for (int p = 0; p < SHARED_P; ++p) {
                float4 x = src[p * D_VEC + t];
                acc.x += x.x; acc.y += x.y; acc.z += x.z; acc.w += x.w;
            }
            const float inv = 1.0f / (float)SHARED_P;
            acc.x *= inv; acc.y *= inv; acc.z *= inv; acc.w *= inv;
            reinterpret_cast<float4*>(g_shared_mean)[st * D_VEC + t] = acc;
        }
    }
}

// 256-bit proto load, L2 evict_last (pins proto table in L2 across replays).
#define LDP256(i, row)                                                        \
    asm volatile("ld.global.nc.L2::evict_last.v8.b32 "                       \
                 "{%0,%1,%2,%3,%4,%5,%6,%7}, [%8];"                          \
                 : "=r"(x##i[0]), "=r"(x##i[1]), "=r"(x##i[2]), "=r"(x##i[3]),\
                   "=r"(x##i[4]), "=r"(x##i[5]), "=r"(x##i[6]), "=r"(x##i[7]) \
                 : "l"(pbase + (size_t)(row) * D_DIM));

// ---------------------------------------------------------------------------
// Main kernel: 2 samples per block, 96 lanes per sample (32B granule each).
// Rows 0-3 always loaded (clamped); rows 4-7 behind ONE warp-uniform branch.
// Default cache policy on features/out (stay L2-resident across replays).
// ---------------------------------------------------------------------------
__global__ __launch_bounds__(TPB)
void proto_pool_kernel(const float* __restrict__ features,
                       const float* __restrict__ class_protos,
                       float* __restrict__ out) {
    int b = blockIdx.x * SPB + (threadIdx.x / LPS);  // sample id
    int l = threadIdx.x % LPS;                       // 0..95, floats [l*8, l*8+8)

    // 1) Feature load first — independent (default policy, L2-resident warm).
    const float4* fptr = reinterpret_cast<const float4*>(
        features + (size_t)b * D_DIM + l * 8);
    float4 fa = fptr[0];
    float4 fb = fptr[1];

    // 2) Descriptor (warp-broadcast: 32 lanes cover <=2 samples; L2-hot).
    int4 dd = g_desc[b];
    int   pair = dd.x;
    int   cnt  = dd.y;
    float inv  = __int_as_float(dd.z);
    int   st   = dd.w;

    // 3) Proto burst. Rows 0..3 always (clamped -> duplicates L1-hit),
    //    rows 4..7 only if cnt > 4 (warp-uniform branch, non-divergent).
    int cm1 = max(cnt - 1, 0);
    const float* pbase = class_protos + (size_t)pair * (MAX_P * D_DIM) + l * 8;

    uint32_t x0[8], x1[8], x2[8], x3[8], x4[8], x5[8], x6[8], x7[8];
    LDP256(0, 0)
    LDP256(1, min(1, cm1))
    LDP256(2, min(2, cm1))
    LDP256(3, min(3, cm1))
    bool hi = (cnt > 4);
    if (hi) {
        LDP256(4, 4)
        LDP256(5, min(5, cm1))
        LDP256(6, min(6, cm1))
        LDP256(7, min(7, cm1))
    }

    // 4) Shared-mean (tiny, L2-resident).
    const float4* shp = reinterpret_cast<const float4*>(
        g_shared_mean + st * D_DIM + l * 8);
    float4 sa = shp[0];
    float4 sb = shp[1];
    float sh[8] = {sa.x, sa.y, sa.z, sa.w, sb.x, sb.y, sb.z, sb.w};
    float f[8]  = {fa.x, fa.y, fa.z, fa.w, fb.x, fb.y, fb.z, fb.w};

    // 5) Per-row weights (0 for clamped duplicates / unloaded rows).
    float w0 = (0 < cnt) ? inv : 0.f;
    float w1 = (1 < cnt) ? inv : 0.f;
    float w2 = (2 < cnt) ? inv : 0.f;
    float w3 = (3 < cnt) ? inv : 0.f;
    float w5 = (5 < cnt) ? inv : 0.f;
    float w6 = (6 < cnt) ? inv : 0.f;
    float w7 = (7 < cnt) ? inv : 0.f;

    // 6) Accumulate: low rows first (their loads issued first), then hi rows.
    float r[8];
#pragma unroll
    for (int j = 0; j < 8; ++j) {
        float a = f[j] + 0.5f * sh[j];
        float c = w1 * __uint_as_float(x1[j]);
        a += w0 * __uint_as_float(x0[j]);
        c += w3 * __uint_as_float(x3[j]);
        a += w2 * __uint_as_float(x2[j]);
        r[j] = a + c;
    }
    if (hi) {
#pragma unroll
        for (int j = 0; j < 8; ++j) {
            float a = inv * __uint_as_float(x4[j]);   // row 4 valid iff cnt>4
            float c = w5 * __uint_as_float(x5[j]);
            a += w6 * __uint_as_float(x6[j]);
            c += w7 * __uint_as_float(x7[j]);
            r[j] += a + c;
        }
    }

    // 7) Default-policy stores (write-back, stay dirty in L2 across replays).
    float4* optr = reinterpret_cast<float4*>(out + (size_t)b * D_DIM + l * 8);
    optr[0] = make_float4(r[0], r[1], r[2], r[3]);
    optr[1] = make_float4(r[4], r[5], r[6], r[7]);
}

extern "C" void kernel_launch(void* const* d_in, const int* in_sizes, int n_in,
                              void* d_out, int out_size) {
    const float* features      = (const float*)d_in[0];
    const float* class_protos  = (const float*)d_in[1];
    const float* shared_protos = (const float*)d_in[2];
    const int*   class_ids     = (const int*)d_in[3];
    const int*   stages        = (const int*)d_in[4];
    const int*   proto_counts  = (const int*)d_in[5];
    float* out = (float*)d_out;

    prep_kernel<<<20, 256>>>(shared_protos, class_ids, stages, proto_counts);
    proto_pool_kernel<<<B_SAMPLES / SPB, TPB>>>(features, class_protos, out);
}